// round 1
// baseline (speedup 1.0000x reference)
#include <cuda_runtime.h>

#define NROWS 65536
#define FDIM  64
#define EDIM  16
#define NH1   8
#define NH2   4
#define BN_EPS 1e-5f

// ---- device scratch (no allocs allowed) ----
__device__ float g_xc_sum[FDIM];
__device__ float g_hstat[2 * NH1];        // [0..7]=sum h_j, [8..15]=sum h_j^2
__device__ float g_k[FDIM];               // w2*xc_mean + b2
__device__ float g_U[FDIM * EDIM];        // W1+W2
__device__ float g_Mh[FDIM * 24];         // per f: P[8],Q[8],R[8]
__device__ float g_quad[FDIM * 8];        // per f: m0..m5 (m3..m5 pre-doubled), pad
__device__ float g_fin[32];               // 0..7 alpha, 8..15 beta', 16..23 v, 24 cb
__device__ float g_h[NROWS * NH1];        // 2MB h scratch

// ---------------- K0: zero accumulators (must run every replay) ----------------
__global__ void k_zero() {
    int t = threadIdx.x;
    if (t < FDIM) g_xc_sum[t] = 0.f;
    if (t < 2 * NH1) g_hstat[t] = 0.f;
}

// ---------------- K1: column sums of Xc ----------------
__global__ void __launch_bounds__(256) k_xcsum(const float* __restrict__ Xc) {
    __shared__ float part[4][FDIM];
    int col = threadIdx.x & 63;
    int rg  = threadIdx.x >> 6;           // 0..3
    float acc = 0.f;
    for (int r = blockIdx.x * 4 + rg; r < NROWS; r += gridDim.x * 4)
        acc += Xc[r * FDIM + col];
    part[rg][col] = acc;
    __syncthreads();
    if (threadIdx.x < FDIM) {
        float v = part[0][threadIdx.x] + part[1][threadIdx.x]
                + part[2][threadIdx.x] + part[3][threadIdx.x];
        atomicAdd(&g_xc_sum[threadIdx.x], v);
    }
}

// ---------------- K2: setup derived constants (1 block) ----------------
__global__ void __launch_bounds__(256) k_setup(
    const float* __restrict__ w2, const float* __restrict__ b2,
    const float* __restrict__ W1, const float* __restrict__ W2p,
    const float* __restrict__ B1, const float* __restrict__ B2,
    const float* __restrict__ L1w)
{
    int tid = threadIdx.x;
    for (int idx = tid; idx < FDIM * EDIM; idx += 256)
        g_U[idx] = W1[idx] + W2p[idx];
    __syncthreads();

    if (tid < FDIM) {
        float xcm = g_xc_sum[tid] * (1.0f / NROWS);
        g_k[tid] = w2[tid] * xcm + b2[tid];
        float m0 = 0, m1 = 0, m2 = 0, m3 = 0, m4 = 0, m5 = 0;
        for (int e = 0; e < EDIM; e++) {
            float u = g_U[tid * EDIM + e];
            float x = B1[tid * EDIM + e];
            float y = B2[tid * EDIM + e];
            m0 += u * u; m1 += x * x; m2 += y * y;
            m3 += u * x; m4 += u * y; m5 += x * y;
        }
        g_quad[tid * 8 + 0] = m0;
        g_quad[tid * 8 + 1] = m1;
        g_quad[tid * 8 + 2] = m2;
        g_quad[tid * 8 + 3] = 2.f * m3;
        g_quad[tid * 8 + 4] = 2.f * m4;
        g_quad[tid * 8 + 5] = 2.f * m5;
        g_quad[tid * 8 + 6] = 0.f;
        g_quad[tid * 8 + 7] = 0.f;
    }
    // Mh: P_j(f)=sum_e U[f,e]*L[j,f*16+e]; Q with B1; R with B2
    for (int idx = tid; idx < FDIM * NH1; idx += 256) {
        int f = idx >> 3, j = idx & 7;
        const float* lr = L1w + j * (FDIM * EDIM) + f * EDIM;
        float P = 0, Q = 0, R = 0;
        for (int e = 0; e < EDIM; e++) {
            float l = lr[e];
            P += g_U[f * EDIM + e] * l;
            Q += B1[f * EDIM + e] * l;
            R += B2[f * EDIM + e] * l;
        }
        g_Mh[f * 24 + j]      = P;
        g_Mh[f * 24 + 8 + j]  = Q;
        g_Mh[f * 24 + 16 + j] = R;
    }
}

// ---------------- K3: main per-row pass ----------------
__global__ void __launch_bounds__(256) k_main(
    const float* __restrict__ Xa, const float* __restrict__ Xc,
    const float* __restrict__ w1, const float* __restrict__ b1,
    const float* __restrict__ B1, const float* __restrict__ B2,
    const float* __restrict__ lin1_b, float* __restrict__ out)
{
    __shared__ float4 sS[FDIM * 12];   // per f: U(4x f4), B1(4), B2(4)
    __shared__ float  sMh[FDIM * 24];
    __shared__ float4 sQ[FDIM * 2];
    __shared__ float4 sFF[FDIM];       // w1, b1, k, 0
    __shared__ float  sStat[2 * NH1];

    int tid = threadIdx.x;
    {
        const float4* U4  = (const float4*)g_U;
        const float4* B14 = (const float4*)B1;
        const float4* B24 = (const float4*)B2;
        for (int idx = tid; idx < FDIM * 4; idx += 256) {
            int f = idx >> 2, j = idx & 3;
            sS[f * 12 + j]     = U4[idx];
            sS[f * 12 + 4 + j] = B14[idx];
            sS[f * 12 + 8 + j] = B24[idx];
        }
        for (int idx = tid; idx < FDIM * 24; idx += 256) sMh[idx] = g_Mh[idx];
        const float4* q4 = (const float4*)g_quad;
        for (int idx = tid; idx < FDIM * 2; idx += 256) sQ[idx] = q4[idx];
        if (tid < FDIM) sFF[tid] = make_float4(w1[tid], b1[tid], g_k[tid], 0.f);
        if (tid < 2 * NH1) sStat[tid] = 0.f;
    }
    __syncthreads();

    int i = blockIdx.x * 256 + tid;
    const float4* A4 = (const float4*)Xa + (size_t)i * 16;
    const float4* C4 = (const float4*)Xc + (size_t)i * 16;

    float sE[EDIM];
    float hv[NH1];
    #pragma unroll
    for (int e = 0; e < EDIM; e++) sE[e] = 0.f;
    #pragma unroll
    for (int j = 0; j < NH1; j++) hv[j] = 0.f;
    float q = 0.f, ff = 0.f;

    #pragma unroll 2
    for (int ch = 0; ch < 16; ch++) {
        float4 a4 = A4[ch];
        float4 c4 = C4[ch];
        float av[4] = {a4.x, a4.y, a4.z, a4.w};
        float cv[4] = {c4.x, c4.y, c4.z, c4.w};
        #pragma unroll
        for (int u = 0; u < 4; u++) {
            int f = ch * 4 + u;
            float a = av[u], c = cv[u];
            float ac = a * c;
            // fm_first: w1*ac + b1*c + k*a
            float4 w = sFF[f];
            ff += ac * w.x;
            ff += c * w.y;
            ff += a * w.z;
            // quadratic term: sum_e emb^2 contribution of this f
            float4 q0 = sQ[f * 2], q1 = sQ[f * 2 + 1];
            q += (ac * ac) * q0.x;
            q += (c * c)   * q0.y;
            q += (a * a)   * q0.z;
            q += (ac * c)  * q0.w;
            q += (ac * a)  * q1.x;
            q += ac        * q1.y;
            // s[e] matvec
            const float4* sp = &sS[f * 12];
            #pragma unroll
            for (int e4 = 0; e4 < 4; e4++) {
                float4 uu  = sp[e4];
                float4 bb1 = sp[4 + e4];
                float4 bb2 = sp[8 + e4];
                sE[e4 * 4 + 0] += ac * uu.x + c * bb1.x + a * bb2.x;
                sE[e4 * 4 + 1] += ac * uu.y + c * bb1.y + a * bb2.y;
                sE[e4 * 4 + 2] += ac * uu.z + c * bb1.z + a * bb2.z;
                sE[e4 * 4 + 3] += ac * uu.w + c * bb1.w + a * bb2.w;
            }
            // h matvec
            const float* mh = &sMh[f * 24];
            #pragma unroll
            for (int j = 0; j < NH1; j++)
                hv[j] += ac * mh[j] + c * mh[8 + j] + a * mh[16 + j];
        }
    }

    float ss = 0.f;
    #pragma unroll
    for (int e = 0; e < EDIM; e++) ss += sE[e] * sE[e];
    float fm2 = 0.5f * (ss - q) * (1.0f / EDIM);
    out[i] = ff * (1.0f / FDIM) + fm2;

    #pragma unroll
    for (int j = 0; j < NH1; j++) hv[j] += __ldg(&lin1_b[j]);
    float4* hout = (float4*)g_h + (size_t)i * 2;
    hout[0] = make_float4(hv[0], hv[1], hv[2], hv[3]);
    hout[1] = make_float4(hv[4], hv[5], hv[6], hv[7]);

    // BN stat partials: warp butterfly reduce, then shared, then global
    float st[16];
    #pragma unroll
    for (int j = 0; j < NH1; j++) { st[j] = hv[j]; st[8 + j] = hv[j] * hv[j]; }
    #pragma unroll
    for (int off = 16; off; off >>= 1) {
        #pragma unroll
        for (int j = 0; j < 16; j++)
            st[j] += __shfl_xor_sync(0xffffffffu, st[j], off);
    }
    if ((tid & 31) == 0) {
        #pragma unroll
        for (int j = 0; j < 16; j++) atomicAdd(&sStat[j], st[j]);
    }
    __syncthreads();
    if (tid < 16) atomicAdd(&g_hstat[tid], sStat[tid]);
}

// ---------------- K4: BN finalize + fold lin2 ----------------
__global__ void k_fin(const float* __restrict__ gamma, const float* __restrict__ beta,
                      const float* __restrict__ l2w, const float* __restrict__ l2b)
{
    int tid = threadIdx.x;
    if (tid < NH1) {
        float mu  = g_hstat[tid] * (1.0f / NROWS);
        float var = g_hstat[NH1 + tid] * (1.0f / NROWS) - mu * mu;
        float rs  = rsqrtf(var + BN_EPS);
        float al  = gamma[tid] * rs;
        g_fin[tid] = al;
        g_fin[8 + tid] = beta[tid] - mu * al;
        float v = 0.f;
        for (int j = 0; j < NH2; j++) v += l2w[j * NH1 + tid];
        g_fin[16 + tid] = v * (1.0f / NH2);
    }
    if (tid == 0) {
        float cb = 0.f;
        for (int j = 0; j < NH2; j++) cb += l2b[j];
        g_fin[24] = cb * (1.0f / NH2);
    }
}

// ---------------- K5: tanh + lin2 epilogue ----------------
__global__ void __launch_bounds__(256) k_deep(float* __restrict__ out)
{
    __shared__ float fin[32];
    if (threadIdx.x < 32) fin[threadIdx.x] = g_fin[threadIdx.x];
    __syncthreads();
    int i = blockIdx.x * 256 + threadIdx.x;
    const float4* h4 = (const float4*)g_h + (size_t)i * 2;
    float4 hA = h4[0], hB = h4[1];
    float hvv[8] = {hA.x, hA.y, hA.z, hA.w, hB.x, hB.y, hB.z, hB.w};
    float acc = fin[24];
    #pragma unroll
    for (int j = 0; j < NH1; j++)
        acc += fin[16 + j] * tanhf(fin[j] * hvv[j] + fin[8 + j]);
    out[i] += acc;
}

extern "C" void kernel_launch(void* const* d_in, const int* in_sizes, int n_in,
                              void* d_out, int out_size)
{
    const float* Xa     = (const float*)d_in[0];
    const float* Xc     = (const float*)d_in[1];
    const float* w1     = (const float*)d_in[2];
    const float* b1     = (const float*)d_in[3];
    const float* w2     = (const float*)d_in[4];
    const float* b2     = (const float*)d_in[5];
    const float* W1     = (const float*)d_in[6];
    const float* B1     = (const float*)d_in[7];
    const float* W2     = (const float*)d_in[8];
    const float* B2     = (const float*)d_in[9];
    const float* L1w    = (const float*)d_in[10];
    const float* L1b    = (const float*)d_in[11];
    const float* g1     = (const float*)d_in[12];
    const float* be1    = (const float*)d_in[13];
    const float* L2w    = (const float*)d_in[14];
    const float* L2b    = (const float*)d_in[15];
    float* out = (float*)d_out;

    k_zero<<<1, 128>>>();
    k_xcsum<<<512, 256>>>(Xc);
    k_setup<<<1, 256>>>(w2, b2, W1, W2, B1, B2, L1w);
    k_main<<<NROWS / 256, 256>>>(Xa, Xc, w1, b1, B1, B2, L1b, out);
    k_fin<<<1, 32>>>(g1, be1, L2w, L2b);
    k_deep<<<NROWS / 256, 256>>>(out);
}